// round 2
// baseline (speedup 1.0000x reference)
#include <cuda_runtime.h>
#include <math.h>

#define BB   32
#define TT   512
#define CC   4233
#define UU   64
#define LABT 129            // 2*U+1
#define NT   160            // threads per DP block (5 warps)
#define NW   (NT/32)        // 5 warps
#define CHUNK 16
#define NCH  (TT/CHUNK)     // 32
#define EC   (CHUNK*LABT)   // 2064 floats per chunk
#define KREG 13             // ceil(EC/NT)

#define PADV (-3.4028234663852886e38f)  // jnp.finfo(float32).min

// compact gathered emissions: [B][T][labT], contiguous
__device__ float g_emit[(size_t)BB * TT * LABT];

// ---------------------------------------------------------------------------
// Phase 1: gather emit[b,t,j] = logit[b,t, ext_idx[b,j]]  (full-chip, HBM)
// ---------------------------------------------------------------------------
__global__ void gather_kernel(const float* __restrict__ logit,
                              const int*   __restrict__ label,
                              const int*   __restrict__ blankp)
{
    const int blank = blankp ? *blankp : 0;
    unsigned idx = blockIdx.x * blockDim.x + threadIdx.x;
    const unsigned total = (unsigned)BB * TT * LABT;
    if (idx >= total) return;

    unsigned j  = idx % LABT;
    unsigned bt = idx / LABT;          // b*T + t  (T=512 -> b = bt>>9)

    int c;
    if (j & 1) {
        int l = label[(j >> 1) * BB + (bt >> 9)];
        if (l == blank) l = -1;        // pad sentinel, wraps like jnp % C
        c = l % CC; if (c < 0) c += CC;
    } else {
        c = blank % CC; if (c < 0) c += CC;
    }
    g_emit[idx] = logit[(size_t)bt * CC + (unsigned)c];
}

// ---------------------------------------------------------------------------
// Phase 2: forward DP + Viterbi backtrack + align write. One block per batch.
// Backpointer deltas (0/1/2) packed 2-bit via warp ballots: 20 KB smem.
// ---------------------------------------------------------------------------
__global__ __launch_bounds__(NT, 1)
void dp_kernel(const int* __restrict__ label,
               const int* __restrict__ blankp,
               float* __restrict__ out_align,
               float* __restrict__ out_loss)
{
    __shared__ unsigned dw[TT][2 * NW];          // [t][warp*2 + {bit0,bit1}]
    __shared__ float dpb[2][132];                // [2..130] = positions 0..128
    __shared__ float ech[2][EC];                 // double-buffered emit chunks
    __shared__ unsigned short wi_sm[TT];
    __shared__ int yl_sm;

    const int tid  = threadIdx.x;
    const int lane = tid & 31;
    const int wrp  = tid >> 5;
    const int b    = blockIdx.x;
    const int blank = blankp ? *blankp : 0;

    // ---- per-position cond flag (fixed across time) ----
    bool cond = false;
    if (tid < LABT) {
        int j = tid, ej, ej2;
        if (j & 1) { int l = label[(j >> 1) * BB + b]; ej = (l == blank) ? -1 : l; }
        else         ej = blank;
        if (j >= 2) {
            int j2 = j - 2;
            if (j2 & 1) { int l = label[(j2 >> 1) * BB + b]; ej2 = (l == blank) ? -1 : l; }
            else          ej2 = blank;
        } else ej2 = -1;
        cond = (ej == blank) || (ej == ej2);
    }
    if (tid == 0) {
        int cnt = 0;
        for (int u = 0; u < UU; u++) if (label[u * BB + b] != blank) cnt++;
        yl_sm = 2 * cnt + 1;
    }
    if (tid < 132) { dpb[0][tid] = PADV; dpb[1][tid] = PADV; }

    const float* emitb = g_emit + (size_t)b * TT * LABT;

    // ---- preload chunk 0 ----
    float r[KREG];
    #pragma unroll
    for (int k = 0; k < KREG; k++) {
        int idx = tid + k * NT;
        if (idx < EC) r[k] = emitb[idx];
    }
    #pragma unroll
    for (int k = 0; k < KREG; k++) {
        int idx = tid + k * NT;
        if (idx < EC) ech[0][idx] = r[k];
    }
    __syncthreads();

    // ---- forward DP, software-pipelined emit chunks ----
    int cur = 0;
    for (int c = 0; c < NCH; c++) {
        if (c + 1 < NCH) {                       // issue next chunk loads early
            const float* src = emitb + (size_t)(c + 1) * EC;
            #pragma unroll
            for (int k = 0; k < KREG; k++) {
                int idx = tid + k * NT;
                if (idx < EC) r[k] = src[idx];
            }
        }
        for (int s = 0; s < CHUNK; s++) {
            const int t = c * CHUNK + s;
            float* dpprev = dpb[(t + 1) & 1];
            float* dpcur  = dpb[t & 1];
            unsigned d = 0;
            if (tid < LABT) {
                float e = ech[cur][s * LABT + tid];
                if (t == 0) {
                    dpcur[2 + tid] = (tid < 2) ? e : PADV;
                } else {
                    float v0 = dpprev[2 + tid];  // dp[j]
                    float v1 = dpprev[1 + tid];  // dp[j-1]
                    float v2 = dpprev[tid];      // dp[j-2]
                    float m01 = fmaxf(v0, v1);
                    float m   = cond ? m01 : fmaxf(m01, v2);
                    float a2  = cond ? PADV : (v2 - m);   // exp(PADV)=0 kills term
                    float sum = expf(v0 - m) + expf(v1 - m) + expf(a2);
                    float val = e + m + logf(sum);
                    // first-max argmax (matches jnp.argmax tie-breaking)
                    d = cond ? ((v1 > v0) ? 1u : 0u)
                             : ((v2 > m01) ? 2u : ((v1 > v0) ? 1u : 0u));
                    dpcur[2 + tid] = val;
                }
            }
            // pack delta bits: 2 ballots per warp (all 32 lanes participate)
            unsigned b0 = __ballot_sync(0xffffffffu, d & 1u);
            unsigned b1 = __ballot_sync(0xffffffffu, d & 2u);
            if (lane == 0) {
                dw[t][wrp * 2 + 0] = b0;
                dw[t][wrp * 2 + 1] = b1;
            }
            __syncthreads();
        }
        if (c + 1 < NCH) {                       // publish next chunk
            #pragma unroll
            for (int k = 0; k < KREG; k++) {
                int idx = tid + k * NT;
                if (idx < EC) ech[cur ^ 1][idx] = r[k];
            }
        }
        __syncthreads();
        cur ^= 1;
    }

    // ---- loss + Viterbi backtrack (thread 0, smem-resident deltas) ----
    if (tid == 0) {
        const float* dpl = dpb[(TT - 1) & 1];
        int yl = yl_sm;
        float d1 = dpl[2 + yl - 1];
        float d2 = dpl[2 + yl - 2];
        int wi = (d1 > d2) ? (yl - 1) : (yl - 2);
        for (int t = TT - 1; t >= 0; t--) {
            wi_sm[t] = (unsigned short)wi;
            int w = wi >> 5, ln = wi & 31;
            int d = (int)((dw[t][w * 2] >> ln) & 1u)
                  | (int)(((dw[t][w * 2 + 1] >> ln) & 1u) << 1);
            wi -= d;
        }
        float mm  = fmaxf(d1, d2);
        float lse = mm + log1pf(expf(-fabsf(d1 - d2)));
        if (out_loss) out_loss[b] = -2.0f * lse / (float)(yl - 1);
    }
    __syncthreads();

    // ---- write one-hot alignment, dense coalesced ----
    float* ob = out_align + (size_t)b * TT * LABT;
    int t = 0, j = tid;
    while (j >= LABT) { j -= LABT; t++; }
    for (int n = tid; n < TT * LABT; n += NT) {
        ob[n] = (j == (int)wi_sm[t]) ? 1.0f : 0.0f;
        j += NT;
        while (j >= LABT) { j -= LABT; t++; }
    }
}

// ---------------------------------------------------------------------------
extern "C" void kernel_launch(void* const* d_in, const int* in_sizes, int n_in,
                              void* d_out, int out_size)
{
    const float* logit  = (const float*)d_in[0];
    const int*   label  = (const int*)d_in[1];
    const int*   blankp = (n_in >= 3) ? (const int*)d_in[2] : nullptr;

    float* out       = (float*)d_out;
    const size_t align_elems = (size_t)BB * TT * LABT;   // 2,113,536
    float* out_loss  = ((size_t)out_size >= align_elems + BB) ? (out + align_elems)
                                                              : nullptr;

    const int total = BB * TT * LABT;
    gather_kernel<<<(total + 255) / 256, 256>>>(logit, label, blankp);
    dp_kernel<<<BB, NT>>>(label, blankp, out, out_loss);
}